// round 1
// baseline (speedup 1.0000x reference)
#include <cuda_runtime.h>

// Problem constants
#define TT   1024
#define BB   16
#define CC   1024
#define HH   16
#define KW   7
#define PADL 6
#define MM   (TT * BB)       // 16384 rows of the GEMM
#define NN   (HH * KW)       // 112 outputs per row
#define KD   1024            // reduction dim

// GEMM tiling
#define BM 64
#define BK 32
#define GEMM_BLOCKS (MM / BM)        // 256
#define ZERO_BLOCKS 2048
#define DENSE_F4    ((size_t)BB * HH * TT * TT / 4)   // 67108864 float4

// scratch: softmaxed conv weights, layout [m = t*B+b][o = h*7+k]
__device__ float g_wsm[(size_t)MM * NN];

// ---------------------------------------------------------------------------
// Kernel 1: fused  (a) fp32 GEMM  w = x @ W^T  + masked softmax over K=7
//                  (b) zero-fill of the dense band matrix (overlapped blocks)
// ---------------------------------------------------------------------------
__global__ __launch_bounds__(256)
void k1_gemm_softmax_zero(const float* __restrict__ x,
                          const float* __restrict__ W,
                          float* __restrict__ dense)
{
    if (blockIdx.x >= GEMM_BLOCKS) {
        // ---- zero-fill branch: stream zeros into dense ----
        size_t per  = DENSE_F4 / ZERO_BLOCKS;                      // 32768 f4 per block
        size_t base = (size_t)(blockIdx.x - GEMM_BLOCKS) * per;
        float4 z = make_float4(0.f, 0.f, 0.f, 0.f);
        float4* d4 = (float4*)dense;
        for (size_t i = threadIdx.x; i < per; i += 256)
            d4[base + i] = z;
        return;
    }

    // ---- GEMM branch ----
    __shared__ __align__(16) float As[BK][BM + 4];   // row stride 68 floats
    __shared__ float Bs[BK][NN + 1];                 // row stride 113 floats (conflict-free)

    const int tid = threadIdx.x;
    const int tx  = tid & 15;    // head index h (owns all 7 k's of that head)
    const int ty  = tid >> 4;    // m micro-group (4 rows)
    const int mBase = blockIdx.x * BM;

    float acc[4][7];
#pragma unroll
    for (int i = 0; i < 4; i++)
#pragma unroll
        for (int j = 0; j < 7; j++) acc[i][j] = 0.f;

    const int kk = tid & 31;     // loader column within BK tile
    const int ld = tid >> 5;     // loader row phase (0..7)

    for (int k0 = 0; k0 < KD; k0 += BK) {
        // load A tile (64 x 32), transposed into As[kk][m]; 128B coalesced per warp
#pragma unroll
        for (int rr = 0; rr < BM / 8; rr++) {
            int r = ld + rr * 8;
            As[kk][r] = x[(size_t)(mBase + r) * KD + k0 + kk];
        }
        // load B tile (112 x 32), transposed into Bs[kk][o]; W stays L2-resident
#pragma unroll
        for (int oo = 0; oo < NN / 8; oo++) {
            int o = ld + oo * 8;
            Bs[kk][o] = W[(size_t)o * KD + k0 + kk];
        }
        __syncthreads();

#pragma unroll 8
        for (int p = 0; p < BK; p++) {
            float4 a = *(const float4*)&As[p][ty * 4];
            float bv[7];
#pragma unroll
            for (int j = 0; j < 7; j++) bv[j] = Bs[p][tx * 7 + j];
#pragma unroll
            for (int j = 0; j < 7; j++) {
                acc[0][j] += a.x * bv[j];
                acc[1][j] += a.y * bv[j];
                acc[2][j] += a.z * bv[j];
                acc[3][j] += a.w * bv[j];
            }
        }
        __syncthreads();
    }

    // ---- epilogue: per-(m, head) masked softmax over its 7 logits ----
#pragma unroll
    for (int i = 0; i < 4; i++) {
        int m = mBase + ty * 4 + i;
        int t = m >> 4;                       // m = t*B + b, B = 16
        int kmin = PADL - t;                  // k valid iff t + k - PADL >= 0
        if (kmin < 0) kmin = 0;

        float mx = -1e30f;
#pragma unroll
        for (int k = 0; k < 7; k++)
            if (k >= kmin && acc[i][k] > mx) mx = acc[i][k];

        float e[7];
        float s = 0.f;
#pragma unroll
        for (int k = 0; k < 7; k++) {
            e[k] = (k >= kmin) ? __expf(acc[i][k] - mx) : 0.f;
            s += e[k];
        }
        float inv = 1.f / s;
        float* wp = &g_wsm[(size_t)m * NN + tx * 7];
#pragma unroll
        for (int k = 0; k < 7; k++)
            wp[k] = e[k] * inv;
    }
}

// ---------------------------------------------------------------------------
// Kernel 2: out[t,b,:] = sum_k wsm[t,b,h,k] * x[max(t-6+k,0), b, :]
//           + scatter the 7-wide band of wsm into dense (zeros already laid)
// One block per (t, b); 256 threads, one float4 of C each.
// ---------------------------------------------------------------------------
__global__ __launch_bounds__(256)
void k2_out_band(const float* __restrict__ x,
                 float* __restrict__ out,
                 float* __restrict__ dense)
{
    const int t   = blockIdx.x;
    const int b   = blockIdx.y;
    const int tid = threadIdx.x;

    __shared__ float sw[NN];
    if (tid < NN)
        sw[tid] = g_wsm[(size_t)(t * BB + b) * NN + tid];
    __syncthreads();

    const int h = tid >> 4;                 // c = 4*tid, head = c/64
    const float4* x4 = (const float4*)x;

    float4 acc = make_float4(0.f, 0.f, 0.f, 0.f);
#pragma unroll
    for (int k = 0; k < 7; k++) {
        int pos = t - PADL + k;
        if (pos < 0) pos = 0;               // weight is exactly 0 there
        float wk = sw[h * 7 + k];
        float4 v = x4[((size_t)(pos * BB + b) << 8) + tid];
        acc.x += wk * v.x;
        acc.y += wk * v.y;
        acc.z += wk * v.z;
        acc.w += wk * v.w;
    }
    float4* out4 = (float4*)out;
    out4[((size_t)(t * BB + b) << 8) + tid] = acc;

    // band scatter: dense[b*H+h][t][t-6+k] = wsm[t,b,h,k] for valid k
    if (tid < NN) {
        int hh  = tid / 7;
        int k   = tid - hh * 7;
        int col = t - PADL + k;
        if (col >= 0) {
            dense[((size_t)(b * HH + hh) << 20) + ((size_t)t << 10) + col] = sw[tid];
        }
    }
}

// ---------------------------------------------------------------------------
extern "C" void kernel_launch(void* const* d_in, const int* in_sizes, int n_in,
                              void* d_out, int out_size)
{
    const float* x = (const float*)d_in[0];   // (T, B, C) fp32
    const float* W = (const float*)d_in[1];   // (H*K, C)  fp32
    float* out   = (float*)d_out;             // first T*B*C floats
    float* dense = out + (size_t)MM * CC;     // then (B*H, T, T) floats

    k1_gemm_softmax_zero<<<GEMM_BLOCKS + ZERO_BLOCKS, 256>>>(x, W, dense);

    dim3 g2(TT, BB);
    k2_out_band<<<g2, 256>>>(x, out, dense);
}